// round 2
// baseline (speedup 1.0000x reference)
#include <cuda_runtime.h>
#include <cuda_fp16.h>

#define B_SZ    512
#define FEATS   30
#define NNZ     (B_SZ * FEATS)
#define FT_OUT  512
#define N_FEAT  40960
#define N_VFEAT 640

// Transposed fp16 weight tables (static device globals — no runtime allocation).
__device__ __half g_ftwT[(size_t)N_FEAT * FT_OUT];    // [col][k], 42 MB
__device__ __half g_fftwT[(size_t)N_VFEAT * FT_OUT];  // [col][k], 0.64 MB

// ---------------------------------------------------------------------------
// Kernel 1: tiled transpose fp32 [FT_OUT, C] -> fp16 [C, FT_OUT]
// 64x64 tile, float4 coalesced reads, half2 coalesced 128B writes per warp.
// ---------------------------------------------------------------------------
template <int C, bool IS_FT>
__global__ void __launch_bounds__(256) transpose_half_kernel(const float* __restrict__ W) {
    __shared__ float tile[64][68];  // [c_local][k_local], padded
    __half* out = IS_FT ? g_ftwT : g_fftwT;

    const int c0 = blockIdx.x * 64;
    const int k0 = blockIdx.y * 64;

    // Load 64 k-rows x 64 cols as float4 (coalesced along the contiguous col dim)
    #pragma unroll
    for (int i = threadIdx.x; i < 64 * 16; i += 256) {
        int kl = i >> 4;            // 0..63
        int cq = (i & 15) << 2;     // 0,4,...,60
        float4 v = *reinterpret_cast<const float4*>(W + (size_t)(k0 + kl) * C + c0 + cq);
        tile[cq + 0][kl] = v.x;
        tile[cq + 1][kl] = v.y;
        tile[cq + 2][kl] = v.z;
        tile[cq + 3][kl] = v.w;
    }
    __syncthreads();

    // Store: each warp writes one c-row of 64 halfs = 128B contiguous
    #pragma unroll
    for (int i = threadIdx.x; i < 64 * 32; i += 256) {
        int cl = i >> 5;            // 0..63
        int kh = i & 31;            // half2 index within row
        __half2 h = __floats2half2_rn(tile[cl][2 * kh], tile[cl][2 * kh + 1]);
        *reinterpret_cast<__half2*>(out + (size_t)(c0 + cl) * FT_OUT + k0 + 2 * kh) = h;
    }
}

// ---------------------------------------------------------------------------
// Kernel 2: fused embedding-bag gather + bias + clip + output dot + sigmoid.
// One CTA per batch row. 256 threads; thread t owns k = {2t, 2t+1} (one half2).
// All gather loads are 128B/warp coalesced rows of the transposed tables.
// ---------------------------------------------------------------------------
__global__ void __launch_bounds__(256) halfkp_forward_kernel(
    const int*   __restrict__ stm_idx,   // [2, NNZ]; cols at offset NNZ
    const int*   __restrict__ nstm_idx,  // [2, NNZ]
    const float* __restrict__ values,    // [NNZ]
    const float* __restrict__ ft_b,      // [512]
    const float* __restrict__ fft_b,     // [512]
    const float* __restrict__ out_w,     // [1, 1024]
    const float* __restrict__ out_b,     // [1]
    float*       __restrict__ out)       // [512, 1]
{
    const int b = blockIdx.x;
    const int t = threadIdx.x;

    __shared__ int   s_cs[FEATS], s_cn[FEATS];
    __shared__ int   s_vs[FEATS], s_vn[FEATS];  // precomputed col % N_VFEAT
    __shared__ float s_v[FEATS];

    if (t < FEATS) {
        int cs = stm_idx[NNZ + b * FEATS + t];
        int cn = nstm_idx[NNZ + b * FEATS + t];
        s_cs[t] = cs;
        s_cn[t] = cn;
        s_vs[t] = cs % N_VFEAT;
        s_vn[t] = cn % N_VFEAT;
        s_v[t]  = values[b * FEATS + t];
    }
    __syncthreads();

    const __half2* ft2  = reinterpret_cast<const __half2*>(g_ftwT);
    const __half2* fft2 = reinterpret_cast<const __half2*>(g_fftwT);
    const int HROW = FT_OUT / 2;  // 256 half2 per table row

    float asx = 0.f, asy = 0.f;   // stm accumulator (k0, k1)
    float anx = 0.f, any_ = 0.f;  // nstm accumulator

    #pragma unroll 6
    for (int f = 0; f < FEATS; f++) {
        const int   cs = s_cs[f], cn = s_cn[f];
        const int   vs = s_vs[f], vn = s_vn[f];
        const float v  = s_v[f];

        float2 ws = __half22float2(__ldg(&ft2 [(size_t)cs * HROW + t]));
        float2 wn = __half22float2(__ldg(&ft2 [(size_t)cn * HROW + t]));
        float2 gs = __half22float2(__ldg(&fft2[(size_t)vs * HROW + t]));
        float2 gn = __half22float2(__ldg(&fft2[(size_t)vn * HROW + t]));

        asx  += v * (ws.x + gs.x);
        asy  += v * (ws.y + gs.y);
        anx  += v * (wn.x + gn.x);
        any_ += v * (wn.y + gn.y);
    }

    const int k0 = 2 * t, k1 = k0 + 1;
    const float b0 = ft_b[k0] + fft_b[k0];
    const float b1 = ft_b[k1] + fft_b[k1];

    const float hs0 = __saturatef(asx  + b0);
    const float hs1 = __saturatef(asy  + b1);
    const float hn0 = __saturatef(anx  + b0);
    const float hn1 = __saturatef(any_ + b1);

    float z = hs0 * out_w[k0] + hs1 * out_w[k1]
            + hn0 * out_w[FT_OUT + k0] + hn1 * out_w[FT_OUT + k1];

    // Block reduction (8 warps)
    #pragma unroll
    for (int o = 16; o; o >>= 1) z += __shfl_down_sync(0xffffffffu, z, o);

    __shared__ float red[8];
    if ((t & 31) == 0) red[t >> 5] = z;
    __syncthreads();

    if (t == 0) {
        float s = out_b[0];
        #pragma unroll
        for (int w = 0; w < 8; w++) s += red[w];
        out[b] = 1.0f / (1.0f + expf(-s));
    }
}

// ---------------------------------------------------------------------------
// Launch: transpose both weight tables, then fused forward. Same stream ->
// ordering guaranteed; fully graph-capturable (kernel launches only).
// ---------------------------------------------------------------------------
extern "C" void kernel_launch(void* const* d_in, const int* in_sizes, int n_in,
                              void* d_out, int out_size) {
    const int*   stm_idx  = (const int*)  d_in[0];
    const int*   nstm_idx = (const int*)  d_in[1];
    const float* values   = (const float*)d_in[2];
    const float* ft_w     = (const float*)d_in[3];
    const float* ft_b     = (const float*)d_in[4];
    const float* fft_w    = (const float*)d_in[5];
    const float* fft_b    = (const float*)d_in[6];
    const float* out_w    = (const float*)d_in[7];
    const float* out_b    = (const float*)d_in[8];
    float*       out      = (float*)d_out;

    (void)in_sizes; (void)n_in; (void)out_size;

    transpose_half_kernel<N_FEAT, true>
        <<<dim3(N_FEAT / 64, FT_OUT / 64), 256>>>(ft_w);
    transpose_half_kernel<N_VFEAT, false>
        <<<dim3(N_VFEAT / 64, FT_OUT / 64), 256>>>(fft_w);

    halfkp_forward_kernel<<<B_SZ, 256>>>(
        stm_idx, nstm_idx, values, ft_b, fft_b, out_w, out_b, out);
}

// round 3
// speedup vs baseline: 1.2074x; 1.2074x over previous
#include <cuda_runtime.h>
#include <cuda_fp16.h>

#define B_SZ    512
#define FEATS   30
#define NNZ     (B_SZ * FEATS)
#define FT_OUT  512
#define N_FEAT  40960
#define N_VFEAT 640
#define KPAIRS  (FT_OUT / 2)   // 256

// Per-(k-pair, batch-row) partial output contributions. 512 KB static scratch.
__device__ float g_partial[KPAIRS * B_SZ];

// Dynamic smem layout: __half2 sft[N_FEAT]; __half2 sfft[N_VFEAT];
#define SMEM_BYTES ((N_FEAT + N_VFEAT) * 4)

static __device__ __forceinline__ unsigned h2u(__half2 h) {
    return *reinterpret_cast<unsigned*>(&h);
}

// ---------------------------------------------------------------------------
// Kernel 1: one CTA per k-pair. Stream ft_w rows {2kp, 2kp+1} into smem as
// interleaved half2 (sft[c] = (w[k0][c], w[k1][c])), then every thread
// (= one batch row) does the sparse embedding-bag over 30 stm + 30 nstm
// features with random LDS lookups, applies bias + clip, and writes its
// out_w-weighted partial contribution to scratch.
// ---------------------------------------------------------------------------
__global__ void __launch_bounds__(512, 1) halfkp_pair_kernel(
    const int*   __restrict__ stm_idx,   // [2, NNZ]; cols at offset NNZ
    const int*   __restrict__ nstm_idx,  // [2, NNZ]
    const float* __restrict__ values,    // [NNZ]
    const float* __restrict__ ft_w,      // [512, 40960]
    const float* __restrict__ ft_b,      // [512]
    const float* __restrict__ fft_w,     // [512, 640]
    const float* __restrict__ fft_b,     // [512]
    const float* __restrict__ out_w)     // [1, 1024]
{
    extern __shared__ char smem_raw[];
    __half2* sft  = reinterpret_cast<__half2*>(smem_raw);
    __half2* sfft = sft + N_FEAT;

    const int kp = blockIdx.x;
    const int k0 = 2 * kp;
    const int t  = threadIdx.x;

    // ---- Load ft_w rows k0, k0+1 -> interleaved half2 table (coalesced) ----
    {
        const float4* r0 = reinterpret_cast<const float4*>(ft_w + (size_t)k0 * N_FEAT);
        const float4* r1 = reinterpret_cast<const float4*>(ft_w + (size_t)(k0 + 1) * N_FEAT);
        uint4* dst = reinterpret_cast<uint4*>(sft);
        #pragma unroll
        for (int i = 0; i < N_FEAT / 4 / 512; i++) {   // 20 iterations
            const int idx = t + i * 512;
            float4 a = __ldg(r0 + idx);
            float4 b = __ldg(r1 + idx);
            uint4 p;
            p.x = h2u(__floats2half2_rn(a.x, b.x));
            p.y = h2u(__floats2half2_rn(a.y, b.y));
            p.z = h2u(__floats2half2_rn(a.z, b.z));
            p.w = h2u(__floats2half2_rn(a.w, b.w));
            dst[idx] = p;
        }
    }

    // ---- Load fft_w rows k0, k0+1 (640 cols) ----
    if (t < N_VFEAT / 4) {   // 160 threads, one float4 per row each
        const float4* r0 = reinterpret_cast<const float4*>(fft_w + (size_t)k0 * N_VFEAT);
        const float4* r1 = reinterpret_cast<const float4*>(fft_w + (size_t)(k0 + 1) * N_VFEAT);
        float4 a = __ldg(r0 + t);
        float4 b = __ldg(r1 + t);
        uint4 p;
        p.x = h2u(__floats2half2_rn(a.x, b.x));
        p.y = h2u(__floats2half2_rn(a.y, b.y));
        p.z = h2u(__floats2half2_rn(a.z, b.z));
        p.w = h2u(__floats2half2_rn(a.w, b.w));
        reinterpret_cast<uint4*>(sfft)[t] = p;
    }

    __syncthreads();

    // ---- Sparse accumulate: thread t = batch row t ----
    const int base = t * FEATS;
    float asx = 0.f, asy = 0.f, anx = 0.f, any_ = 0.f;

    #pragma unroll
    for (int c = 0; c < 2; c++) {
        int   cs[15], cn[15];
        float vv[15];
        #pragma unroll
        for (int f = 0; f < 15; f++) {
            const int e = base + c * 15 + f;
            cs[f] = __ldg(stm_idx  + NNZ + e);
            cn[f] = __ldg(nstm_idx + NNZ + e);
            vv[f] = __ldg(values + e);
        }
        #pragma unroll
        for (int f = 0; f < 15; f++) {
            float2 ws = __half22float2(__hadd2(sft[cs[f]], sfft[cs[f] % N_VFEAT]));
            float2 wn = __half22float2(__hadd2(sft[cn[f]], sfft[cn[f] % N_VFEAT]));
            asx  = fmaf(vv[f], ws.x, asx);
            asy  = fmaf(vv[f], ws.y, asy);
            anx  = fmaf(vv[f], wn.x, anx);
            any_ = fmaf(vv[f], wn.y, any_);
        }
    }

    // ---- Bias + clip + out_w partial dot ----
    const float b0 = __ldg(ft_b + k0)     + __ldg(fft_b + k0);
    const float b1 = __ldg(ft_b + k0 + 1) + __ldg(fft_b + k0 + 1);

    const float hs0 = __saturatef(asx  + b0);
    const float hs1 = __saturatef(asy  + b1);
    const float hn0 = __saturatef(anx  + b0);
    const float hn1 = __saturatef(any_ + b1);

    const float part = hs0 * __ldg(out_w + k0)
                     + hs1 * __ldg(out_w + k0 + 1)
                     + hn0 * __ldg(out_w + FT_OUT + k0)
                     + hn1 * __ldg(out_w + FT_OUT + k0 + 1);

    g_partial[kp * B_SZ + t] = part;
}

// ---------------------------------------------------------------------------
// Kernel 2: reduce the 256 k-pair partials per batch row, add out_b, sigmoid.
// grid=16, block=256: 8 kp-slices x 32 batch rows per block. Deterministic.
// ---------------------------------------------------------------------------
__global__ void __launch_bounds__(256) halfkp_reduce_kernel(
    const float* __restrict__ out_b,
    float*       __restrict__ out)
{
    const int lane  = threadIdx.x & 31;
    const int slice = threadIdx.x >> 5;         // 0..7
    const int b     = blockIdx.x * 32 + lane;

    float s = 0.f;
    #pragma unroll
    for (int i = 0; i < KPAIRS / 8; i++) {      // 32 partials per slice
        s += g_partial[(slice * (KPAIRS / 8) + i) * B_SZ + b];
    }

    __shared__ float red[8][32];
    red[slice][lane] = s;
    __syncthreads();

    if (slice == 0) {
        float tot = __ldg(out_b);
        #pragma unroll
        for (int j = 0; j < 8; j++) tot += red[j][lane];
        out[b] = 1.0f / (1.0f + expf(-tot));
    }
}

// ---------------------------------------------------------------------------
extern "C" void kernel_launch(void* const* d_in, const int* in_sizes, int n_in,
                              void* d_out, int out_size) {
    const int*   stm_idx  = (const int*)  d_in[0];
    const int*   nstm_idx = (const int*)  d_in[1];
    const float* values   = (const float*)d_in[2];
    const float* ft_w     = (const float*)d_in[3];
    const float* ft_b     = (const float*)d_in[4];
    const float* fft_w    = (const float*)d_in[5];
    const float* fft_b    = (const float*)d_in[6];
    const float* out_w    = (const float*)d_in[7];
    const float* out_b    = (const float*)d_in[8];
    float*       out      = (float*)d_out;

    (void)in_sizes; (void)n_in; (void)out_size;

    static bool attr_set = false;
    if (!attr_set) {
        cudaFuncSetAttribute(halfkp_pair_kernel,
                             cudaFuncAttributeMaxDynamicSharedMemorySize, SMEM_BYTES);
        attr_set = true;
    }

    halfkp_pair_kernel<<<KPAIRS, 512, SMEM_BYTES>>>(
        stm_idx, nstm_idx, values, ft_w, ft_b, fft_w, fft_b, out_w);

    halfkp_reduce_kernel<<<B_SZ / 32, 256>>>(out_b, out);
}